// round 11
// baseline (speedup 1.0000x reference)
#include <cuda_runtime.h>
#include <math.h>
#include <cstdint>

// Problem constants
#define B_      32
#define C_IN    8
#define C_OUT   16
#define KK      3
#define PLANES  (B_ * C_IN)               // 256
#define PLANE_ELEMS (512 * 512)           // 262144 floats = 1 MB
#define BPP     4                         // blocks per plane
#define NBLOCKS (PLANES * BPP)            // 1024
#define NTHREADS 256
#define BLOCK_BYTES (PLANE_ELEMS * 4 / BPP)  // 262144 B = 256 KB per block
#define STAGE_BYTES 8192                  // 8 KB stages
#define NSTAGE  4                         // ring depth (issue depth 3)
#define NCHUNK  (BLOCK_BYTES / STAGE_BYTES)  // 32 chunks per block
#define STAGE_F4 (STAGE_BYTES / 16)       // 512 float4 per stage
#define AREA    264196.0f                 // (H+K-1)^2 = 514^2

// Partial sums scratch: fully overwritten every launch.
__device__ float g_partial[NBLOCKS];

__device__ __forceinline__ uint32_t smem_u32(const void* p) {
    return (uint32_t)__cvta_generic_to_shared(p);
}

__device__ __forceinline__ void bulk_issue(uint32_t dst, const char* src,
                                           uint32_t mb) {
    asm volatile("mbarrier.arrive.expect_tx.shared.b64 _, [%0], %1;"
                 :: "r"(mb), "r"((uint32_t)STAGE_BYTES));
    asm volatile("cp.async.bulk.shared::cluster.global.mbarrier::complete_tx::bytes"
                 " [%0], [%1], %2, [%3];"
                 :: "r"(dst), "l"(src), "r"((uint32_t)STAGE_BYTES), "r"(mb)
                 : "memory");
}

__device__ __forceinline__ void mbar_wait(uint32_t mb, uint32_t phase) {
    asm volatile("{\n\t"
                 ".reg .pred p;\n\t"
                 "WL%=:\n\t"
                 "mbarrier.try_wait.parity.shared.b64 p, [%0], %1;\n\t"
                 "@!p bra WL%=;\n\t"
                 "}"
                 :: "r"(mb), "r"(phase));
}

__global__ void __launch_bounds__(NTHREADS) reduce_tma_kernel(const float* __restrict__ x) {
    __shared__ alignas(128) float4   stage[NSTAGE][STAGE_F4];  // 32 KB
    __shared__ alignas(8)   uint64_t mbar[NSTAGE];

    const int tid = threadIdx.x;
    const char* gsrc = (const char*)x + (size_t)blockIdx.x * BLOCK_BYTES;

    if (tid == 0) {
        #pragma unroll
        for (int s = 0; s < NSTAGE; s++)
            asm volatile("mbarrier.init.shared.b64 [%0], 1;"
                         :: "r"(smem_u32(&mbar[s])));
    }
    __syncthreads();   // mbarriers visible to all before any TMA targets them

    // Prologue: fill issue depth (chunks 0..2 into stages 0..2)
    if (tid == 0) {
        #pragma unroll
        for (int c = 0; c < NSTAGE - 1; c++)
            bulk_issue(smem_u32(&stage[c][0]),
                       gsrc + (size_t)c * STAGE_BYTES,
                       smem_u32(&mbar[c]));
    }

    float acc = 0.0f;
    for (int c = 0; c < NCHUNK; c++) {
        const int st = c & (NSTAGE - 1);

        // Refill: stage (c+3)&3 was consumed at iter c-1; the __syncthreads at
        // the end of iter c-1 makes it safe to overwrite now.
        if (tid == 0 && c + NSTAGE - 1 < NCHUNK) {
            const int nc = c + NSTAGE - 1;
            const int ns = nc & (NSTAGE - 1);
            bulk_issue(smem_u32(&stage[ns][0]),
                       gsrc + (size_t)nc * STAGE_BYTES,
                       smem_u32(&mbar[ns]));
        }

        // Wait for chunk c (parity = use-count of this stage mod 2)
        mbar_wait(smem_u32(&mbar[st]), (uint32_t)((c >> 2) & 1));

        // Sum this stage: 512 float4 / 256 threads = 2 per thread (LDS.128)
        float4 a = stage[st][tid];
        float4 b = stage[st][tid + NTHREADS];
        acc += ((a.x + a.y) + (a.z + a.w)) + ((b.x + b.y) + (b.z + b.w));

        __syncthreads();   // everyone done reading stage st before its reissue
    }

    // Block reduction
    #pragma unroll
    for (int off = 16; off > 0; off >>= 1)
        acc += __shfl_xor_sync(0xFFFFFFFFu, acc, off);

    __shared__ float warp_sums[NTHREADS / 32];
    const int lane = tid & 31;
    const int wid  = tid >> 5;
    if (lane == 0) warp_sums[wid] = acc;
    __syncthreads();

    if (wid == 0) {
        float t = (lane < NTHREADS / 32) ? warp_sums[lane] : 0.0f;
        #pragma unroll
        for (int off = 4; off > 0; off >>= 1)
            t += __shfl_xor_sync(0xFFFFFFFFu, t, off);
        if (lane == 0) g_partial[blockIdx.x] = t;
    }
}

__global__ void __launch_bounds__(256) finalize_kernel(const float* __restrict__ w,
                                                       const float* __restrict__ bias,
                                                       float* __restrict__ out) {
    __shared__ float Sx[B_][C_IN];
    __shared__ float Sw[C_OUT][C_IN];
    __shared__ float Sb[C_OUT];

    const int t = threadIdx.x;

    if (t < PLANES) {
        const float4 pv = *reinterpret_cast<const float4*>(&g_partial[t * BPP]);
        Sx[t / C_IN][t % C_IN] = (pv.x + pv.y) + (pv.z + pv.w);
    }
    if (t < C_OUT * C_IN) {
        const float* wp = w + t * (KK * KK);
        float ws = 0.0f;
        #pragma unroll
        for (int k = 0; k < KK * KK; k++) ws += wp[k];
        Sw[t / C_IN][t % C_IN] = ws;
    }
    if (t < C_OUT) Sb[t] = bias[t];
    __syncthreads();

    if (t < B_) {
        const float inv_area = 1.0f / AREA;
        float pooled[C_OUT];
        float mx = -INFINITY;
        #pragma unroll
        for (int co = 0; co < C_OUT; co++) {
            float d = 0.0f;
            #pragma unroll
            for (int ci = 0; ci < C_IN; ci++)
                d = fmaf(Sx[t][ci], Sw[co][ci], d);
            float v = d * inv_area + Sb[co];
            pooled[co] = v;
            mx = fmaxf(mx, v);
        }
        float se = 0.0f;
        #pragma unroll
        for (int co = 0; co < C_OUT; co++)
            se += __expf(pooled[co] - mx);
        out[t] = (mx + logf(se)) * 10.0f;
    }
}

extern "C" void kernel_launch(void* const* d_in, const int* in_sizes, int n_in,
                              void* d_out, int out_size) {
    const float* x     = (const float*)d_in[0];   // (32,8,512,512) fp32
    const float*  w    = (const float*)d_in[1];   // (16,8,3,3) fp32
    const float*  bias = (const float*)d_in[2];   // (16,1,1) fp32
    float* out = (float*)d_out;                   // (32,) fp32

    reduce_tma_kernel<<<NBLOCKS, NTHREADS>>>(x);
    finalize_kernel<<<1, 256>>>(w, bias, out);
}

// round 12
// speedup vs baseline: 1.0554x; 1.0554x over previous
#include <cuda_runtime.h>
#include <math.h>

// Problem constants
#define B_      32
#define C_IN    8
#define C_OUT   16
#define H_      512
#define W_      512
#define KK      3
#define PLANES  (B_ * C_IN)            // 256
#define PLANE_ELEMS (H_ * W_)          // 262144
#define BPP     4                      // blocks per plane (measured-best geometry)
#define NBLOCKS (PLANES * BPP)         // 1024
#define NTHREADS 256
#define CHUNK_F4 (PLANE_ELEMS / 4 / BPP)  // 16384 float4 per block
#define AREA    264196.0f              // (H+K-1)^2 = 514^2

// Partial sums scratch: NBLOCKS floats, fully overwritten every launch.
__device__ float g_partial[NBLOCKS];

__global__ void __launch_bounds__(NTHREADS) reduce_planes_kernel(const float4* __restrict__ x) {
    const int blk   = blockIdx.x;
    const int plane = blk / BPP;
    const int sub   = blk % BPP;
    const float4* p = x + (size_t)plane * (PLANE_ELEMS / 4) + (size_t)sub * CHUNK_F4;

    float s = 0.0f;
    // 16384 float4 / 256 threads = 64 per thread; unroll-8 batches 8 LDG.128
    // per thread (proven MLP sweet spot). .cs = evict-first streaming hint:
    // data is touched exactly once.
    #pragma unroll 8
    for (int i = threadIdx.x; i < CHUNK_F4; i += NTHREADS) {
        float4 v = __ldcs(&p[i]);
        s += (v.x + v.y) + (v.z + v.w);
    }

    // warp reduce
    #pragma unroll
    for (int off = 16; off > 0; off >>= 1)
        s += __shfl_xor_sync(0xFFFFFFFFu, s, off);

    __shared__ float warp_sums[NTHREADS / 32];
    const int lane = threadIdx.x & 31;
    const int wid  = threadIdx.x >> 5;
    if (lane == 0) warp_sums[wid] = s;
    __syncthreads();

    if (wid == 0) {
        float t = (lane < NTHREADS / 32) ? warp_sums[lane] : 0.0f;
        #pragma unroll
        for (int off = 4; off > 0; off >>= 1)
            t += __shfl_xor_sync(0xFFFFFFFFu, t, off);
        if (lane == 0) g_partial[blk] = t;
    }
}

__global__ void __launch_bounds__(256) finalize_kernel(const float* __restrict__ w,
                                                       const float* __restrict__ bias,
                                                       float* __restrict__ out) {
    __shared__ float Sx[B_][C_IN];     // per-(n,ci) full plane sums
    __shared__ float Sw[C_OUT][C_IN];  // per-(co,ci) kernel-tap sums
    __shared__ float Sb[C_OUT];

    const int t = threadIdx.x;

    // All independent global loads issued up front (latency overlap).
    if (t < PLANES) {
        const float4 pv = *reinterpret_cast<const float4*>(&g_partial[t * BPP]);
        Sx[t / C_IN][t % C_IN] = (pv.x + pv.y) + (pv.z + pv.w);
    }
    if (t < C_OUT * C_IN) {
        const float* wp = w + t * (KK * KK);
        float ws = 0.0f;
        #pragma unroll
        for (int k = 0; k < KK * KK; k++) ws += wp[k];
        Sw[t / C_IN][t % C_IN] = ws;
    }
    if (t < C_OUT) Sb[t] = bias[t];
    __syncthreads();

    if (t < B_) {
        const float inv_area = 1.0f / AREA;
        float pooled[C_OUT];
        float mx = -INFINITY;
        #pragma unroll
        for (int co = 0; co < C_OUT; co++) {
            float d = 0.0f;
            #pragma unroll
            for (int ci = 0; ci < C_IN; ci++)
                d = fmaf(Sx[t][ci], Sw[co][ci], d);
            float v = d * inv_area + Sb[co];
            pooled[co] = v;
            mx = fmaxf(mx, v);
        }
        float se = 0.0f;
        #pragma unroll
        for (int co = 0; co < C_OUT; co++)
            se += __expf(pooled[co] - mx);
        out[t] = (mx + logf(se)) * 10.0f;
    }
}

extern "C" void kernel_launch(void* const* d_in, const int* in_sizes, int n_in,
                              void* d_out, int out_size) {
    const float4* x    = (const float4*)d_in[0];  // (32,8,512,512) fp32
    const float*  w    = (const float*)d_in[1];   // (16,8,3,3) fp32
    const float*  bias = (const float*)d_in[2];   // (16,1,1) fp32
    float* out = (float*)d_out;                   // (32,) fp32

    reduce_planes_kernel<<<NBLOCKS, NTHREADS>>>(x);
    finalize_kernel<<<1, 256>>>(w, bias, out);
}